// round 1
// baseline (speedup 1.0000x reference)
#include <cuda_runtime.h>

// VegasMap: piecewise-linear adaptive map + Jacobian.
// y: [B, 16] f32 in [0,1); grid: [16, ninc+1]; inc: [16, ninc]
// out: x [B,16] followed by jac [B]  (reference returns (x, jac))

#define DIM 16

__global__ __launch_bounds__(256)
void vegas_map_kernel(const float4* __restrict__ y4,
                      const float*  __restrict__ grid,
                      const float*  __restrict__ inc,
                      float4*       __restrict__ x4,
                      float*        __restrict__ jac,
                      int B, int ninc)
{
    int b = blockIdx.x * blockDim.x + threadIdx.x;
    if (b >= B) return;

    const float ninc_f = (float)ninc;
    float prod = 1.0f;

#pragma unroll
    for (int q = 0; q < 4; ++q) {
        float4 yv = y4[(size_t)b * 4 + q];
        float ya[4] = {yv.x, yv.y, yv.z, yv.w};
        float xa[4];

#pragma unroll
        for (int j = 0; j < 4; ++j) {
            const int d = q * 4 + j;
            float yn = ya[j] * ninc_f;
            int   iy = (int)floorf(yn);
            float dy = yn - (float)iy;

            // Clamp indices; invalid (iy >= ninc) collapses to the right
            // grid edge by forcing dy = 0 -> x = grid[d, ninc], and the
            // factor uses inc[d, ninc-1]. Exactly matches the reference
            // with a single gather per table.
            bool valid = iy < ninc;
            int ig = min(max(iy, 0), ninc);
            int ii = min(max(iy, 0), ninc - 1);
            if (!valid) dy = 0.0f;

            float g = __ldg(&grid[(size_t)d * (ninc + 1) + ig]);
            float h = __ldg(&inc [(size_t)d * ninc       + ii]);

            xa[j] = fmaf(h, dy, g);
            prod *= h * ninc_f;
        }

        float4 xv;
        xv.x = xa[0]; xv.y = xa[1]; xv.z = xa[2]; xv.w = xa[3];
        x4[(size_t)b * 4 + q] = xv;
    }

    jac[b] = prod;
}

extern "C" void kernel_launch(void* const* d_in, const int* in_sizes, int n_in,
                              void* d_out, int out_size)
{
    const float* y    = (const float*)d_in[0];
    const float* grid = (const float*)d_in[1];
    const float* inc  = (const float*)d_in[2];
    // d_in[3] is the scalar ninc; derive it host-side from sizes instead.

    const int B    = in_sizes[0] / DIM;          // y is [B, 16]
    const int ninc = in_sizes[2] / DIM;          // inc is [16, ninc]

    float* x   = (float*)d_out;
    float* jac = x + (size_t)B * DIM;

    const int threads = 256;
    const int blocks  = (B + threads - 1) / threads;
    vegas_map_kernel<<<blocks, threads>>>(
        (const float4*)y, grid, inc, (float4*)x, jac, B, ninc);
}

// round 3
// speedup vs baseline: 1.0400x; 1.0400x over previous
#include <cuda_runtime.h>

// VegasMap: piecewise-linear adaptive map + Jacobian.
// y: [B, 16] f32 in [0,1); grid: [16, ninc+1]; inc: [16, ninc]
// out: x [B,16] followed by jac [B]
//
// Round-2 change (re-bench after infra failure): pack (grid[d,i], inc[d,i])
// into a float2 table so each per-dim gather is ONE aligned LDG.64 instead
// of two scalar LDG.32 into two arrays. Halves L1 wavefront pressure (the
// measured bottleneck: L1 68.5%, DRAM 20.4%).

#define DIM 16
#define TBL_STRIDE 1024            // row stride in float2 (>= ninc+1, pow2 for cheap addr math)

__device__ float2 g_tbl[DIM * TBL_STRIDE];   // 128 KB device scratch (allowed)

__global__ void pack_tbl_kernel(const float* __restrict__ grid,
                                const float* __restrict__ inc,
                                int ninc)
{
    int i = blockIdx.x * blockDim.x + threadIdx.x;
    int total = DIM * (ninc + 1);
    if (i >= total) return;
    int d = i / (ninc + 1);
    int k = i - d * (ninc + 1);
    float g = grid[(size_t)d * (ninc + 1) + k];
    // For k == ninc (the clamp slot) store inc[ninc-1] so the main kernel's
    // single clamped gather reproduces the reference's out-of-range path.
    float h = inc[(size_t)d * ninc + min(k, ninc - 1)];
    g_tbl[d * TBL_STRIDE + k] = make_float2(g, h);
}

__global__ __launch_bounds__(256)
void vegas_map_kernel(const float4* __restrict__ y4,
                      float4*       __restrict__ x4,
                      float*        __restrict__ jac,
                      int B, int ninc)
{
    int b = blockIdx.x * blockDim.x + threadIdx.x;
    if (b >= B) return;

    const float ninc_f = (float)ninc;
    float prod = 1.0f;

#pragma unroll
    for (int q = 0; q < 4; ++q) {
        float4 yv = y4[(size_t)b * 4 + q];
        float ya[4] = {yv.x, yv.y, yv.z, yv.w};
        float xa[4];

#pragma unroll
        for (int j = 0; j < 4; ++j) {
            const int d = q * 4 + j;
            float yn = ya[j] * ninc_f;
            int   iy = (int)floorf(yn);
            float dy = yn - (float)iy;

            // iy == ninc only when y == 1.0; collapse to right edge with dy=0.
            int ig = min(max(iy, 0), ninc);
            if (iy >= ninc) dy = 0.0f;

            float2 gh = __ldg(&g_tbl[d * TBL_STRIDE + ig]);

            xa[j] = fmaf(gh.y, dy, gh.x);
            prod *= gh.y * ninc_f;
        }

        float4 xv;
        xv.x = xa[0]; xv.y = xa[1]; xv.z = xa[2]; xv.w = xa[3];
        x4[(size_t)b * 4 + q] = xv;
    }

    jac[b] = prod;
}

extern "C" void kernel_launch(void* const* d_in, const int* in_sizes, int n_in,
                              void* d_out, int out_size)
{
    const float* y    = (const float*)d_in[0];
    const float* grid = (const float*)d_in[1];
    const float* inc  = (const float*)d_in[2];

    const int B    = in_sizes[0] / DIM;     // y is [B, 16]
    const int ninc = in_sizes[2] / DIM;     // inc is [16, ninc]

    float* x   = (float*)d_out;
    float* jac = x + (size_t)B * DIM;

    {
        int total = DIM * (ninc + 1);
        int t = 256;
        pack_tbl_kernel<<<(total + t - 1) / t, t>>>(grid, inc, ninc);
    }

    const int threads = 256;
    const int blocks  = (B + threads - 1) / threads;
    vegas_map_kernel<<<blocks, threads>>>(
        (const float4*)y, (float4*)x, jac, B, ninc);
}

// round 4
// speedup vs baseline: 1.3008x; 1.2508x over previous
#include <cuda_runtime.h>

// VegasMap: piecewise-linear adaptive map + Jacobian.
// y: [B, 16] f32; grid: [16, ninc+1]; inc: [16, ninc]
// out: x [B,16] then jac [B]
//
// Round-4: gathers were L1-wavefront bound (~25 line-wavefronts per random
// warp gather). Move the packed (grid,inc) table into shared memory (125KB,
// persistent CTAs) so gathers ride the smem crossbar (~3-6 wavefronts by
// bank-conflict degree). 4-lanes-per-sample layout makes y/x fully coalesced.

#define DIM   16
#define NSM   148
#define TPB   1024

__global__ __launch_bounds__(TPB)
void vegas_map_smem(const float4* __restrict__ y4,
                    const float*  __restrict__ grid,
                    const float*  __restrict__ inc,
                    float4*       __restrict__ x4,
                    float*        __restrict__ jac,
                    int B, int ninc)
{
    extern __shared__ float2 tbl[];          // [DIM][ninc+1] packed (g,h)
    const int np1 = ninc + 1;

    // Cooperative table build: tbl[d][k] = (grid[d,k], inc[d,min(k,ninc-1)]).
    // The k==ninc clamp slot encodes the reference's out-of-range path.
    for (int i = threadIdx.x; i < DIM * np1; i += TPB) {
        int d = i / np1;
        int k = i - d * np1;
        float g = grid[(size_t)d * np1 + k];
        float h = inc [(size_t)d * ninc + min(k, ninc - 1)];
        tbl[i] = make_float2(g, h);
    }
    __syncthreads();

    const float ninc_f = (float)ninc;

    const int t       = blockIdx.x * TPB + threadIdx.x;
    const int g0      = t >> 2;              // sample-group id
    const int q       = t & 3;               // which quarter (4 dims) of the sample
    const int ngroups = (gridDim.x * TPB) >> 2;
    const int niter   = (B + ngroups - 1) / ngroups;   // uniform across all threads

    for (int it = 0; it < niter; ++it) {
        int  s      = g0 + it * ngroups;
        bool active = s < B;

        float4 yv = active ? y4[(size_t)s * 4 + q] : make_float4(0.f, 0.f, 0.f, 0.f);
        float ya[4] = {yv.x, yv.y, yv.z, yv.w};
        float xa[4];
        float prod = 1.0f;

#pragma unroll
        for (int j = 0; j < 4; ++j) {
            const int d = q * 4 + j;
            float yn = ya[j] * ninc_f;
            int   iy = (int)floorf(yn);
            float dy = yn - (float)iy;

            int ig = min(max(iy, 0), ninc);
            if (iy >= ninc) dy = 0.0f;       // collapse to right grid edge

            float2 gh = tbl[d * np1 + ig];   // LDS.64 gather (smem crossbar)

            xa[j] = fmaf(gh.y, dy, gh.x);
            prod *= gh.y * ninc_f;
        }

        // product across the 4-lane group (lanes q=0..3 of this sample)
        prod *= __shfl_xor_sync(0xFFFFFFFF, prod, 1);
        prod *= __shfl_xor_sync(0xFFFFFFFF, prod, 2);

        if (active) {
            float4 xv;
            xv.x = xa[0]; xv.y = xa[1]; xv.z = xa[2]; xv.w = xa[3];
            x4[(size_t)s * 4 + q] = xv;
            if (q == 0) jac[s] = prod;
        }
    }
}

extern "C" void kernel_launch(void* const* d_in, const int* in_sizes, int n_in,
                              void* d_out, int out_size)
{
    const float* y    = (const float*)d_in[0];
    const float* grid = (const float*)d_in[1];
    const float* inc  = (const float*)d_in[2];

    const int B    = in_sizes[0] / DIM;      // y is [B, 16]
    const int ninc = in_sizes[2] / DIM;      // inc is [16, ninc]

    float* x   = (float*)d_out;
    float* jac = x + (size_t)B * DIM;

    const int smem_bytes = DIM * (ninc + 1) * (int)sizeof(float2);  // 128,128 B

    // Opt-in to >48KB dynamic smem. Device-config call: executes immediately,
    // not a stream op, so it is graph-capture safe and idempotent.
    static int attr_set = 0;
    if (!attr_set) {
        cudaFuncSetAttribute(vegas_map_smem,
                             cudaFuncAttributeMaxDynamicSharedMemorySize,
                             smem_bytes);
        attr_set = 1;
    }

    vegas_map_smem<<<NSM, TPB, smem_bytes>>>(
        (const float4*)y, grid, inc, (float4*)x, jac, B, ninc);
}